// round 17
// baseline (speedup 1.0000x reference)
#include <cuda_runtime.h>
#include <cuda_fp16.h>
#include <cstdint>

#define N_MAX 100000
#define E_MAX 1600000
#define C 64
#define NEG_SLOPE 0.2f
#define EPS 1e-16f
#define SCHUNK 1024
#define HB 1024          // hist blocks co-launched with gemm
#define SRB 1024         // scan+reorder blocks

// Scratch (no device allocation allowed)
__device__ __half2 gy_h2[(size_t)N_MAX * (C / 2)];
__device__ float   gy_asrc[N_MAX];
__device__ float   gy_adst[N_MAX];
__device__ int2    gy_se[E_MAX + 4];     // sorted-by-dst: {src, e_bits}
__device__ int     gy_cnt[N_MAX];        // degree histogram
__device__ int     gy_off[N_MAX];        // excl prefix; destroyed by reorder cursor
__device__ int     gy_bsum[128];
__device__ int     gy_is64;
__device__ int     gy_ready;             // scan phase-A published count
__device__ int     gy_done;              // scan phase-B published count

// 1) detect dtype (block 0) + zero counts + reset spin counters
__global__ void kr_init(const int* __restrict__ ei_raw, int N) {
    if (blockIdx.x == 0) {
        __shared__ int nz[256];
        int t = threadIdx.x;
        int acc = 0;
        for (int k = t; k < 2048; k += 256) acc |= ei_raw[2 * k + 1];
        nz[t] = acc;
        __syncthreads();
        for (int s = 128; s > 0; s >>= 1) {
            if (t < s) nz[t] |= nz[t + s];
            __syncthreads();
        }
        if (t == 0) {
            gy_is64 = (nz[0] == 0) ? 1 : 0;
            gy_ready = 0;
            gy_done = 0;
        }
    }
    for (int i = blockIdx.x * blockDim.x + threadIdx.x; i < N;
         i += gridDim.x * blockDim.x)
        gy_cnt[i] = 0;
}

// 2) fused: blocks [0,HB) histogram dst; blocks [HB,HB+gemmB) gemm tiles
//    GEMM: 2 cols/thread via float2 (halves LDS per FMA; direct half2 store)
__global__ __launch_bounds__(256) void kr_gemm_hist(
    const float* __restrict__ x, const float* __restrict__ W,
    const float* __restrict__ att_src, const float* __restrict__ att_dst,
    const int* __restrict__ ei, int E, int N)
{
    __shared__ float Ws[C * C];
    __shared__ float xs[32 * C];

    if (blockIdx.x < HB) {
        int is64 = gy_is64;
        int tid0 = blockIdx.x * blockDim.x + threadIdx.x;
        int stride = HB * blockDim.x;
        if (!is64) {
            const int4* dst4 = (const int4*)(ei + E);
            int E4 = E >> 2;
            for (int i = tid0; i < E4; i += stride) {
                int4 d4 = dst4[i];
                int d0 = ((unsigned)d4.x < (unsigned)N) ? d4.x : 0;
                int d1 = ((unsigned)d4.y < (unsigned)N) ? d4.y : 0;
                int d2 = ((unsigned)d4.z < (unsigned)N) ? d4.z : 0;
                int d3 = ((unsigned)d4.w < (unsigned)N) ? d4.w : 0;
                atomicAdd(&gy_cnt[d0], 1);
                atomicAdd(&gy_cnt[d1], 1);
                atomicAdd(&gy_cnt[d2], 1);
                atomicAdd(&gy_cnt[d3], 1);
            }
            for (int i = (E4 << 2) + tid0; i < E; i += stride) {
                int d = ei[E + i];
                d = ((unsigned)d < (unsigned)N) ? d : 0;
                atomicAdd(&gy_cnt[d], 1);
            }
        } else {
            const long long* el = (const long long*)ei;
            for (int i = tid0; i < E; i += stride) {
                int d = (int)el[E + i];
                d = ((unsigned)d < (unsigned)N) ? d : 0;
                atomicAdd(&gy_cnt[d], 1);
            }
        }
        return;
    }

    int gb = blockIdx.x - HB;
    int tid  = threadIdx.x;
    int lane = tid & 31;          // column-pair index (cols 2*lane, 2*lane+1)
    int wg   = tid >> 5;          // warp 0..7, handles rows wg*4..wg*4+3

    for (int i = tid; i < C * C; i += 256) Ws[i] = W[i];
    int row0 = gb * 32;
    int nrows = min(32, N - row0);
    if (nrows <= 0) return;
    for (int i = tid; i < nrows * C; i += 256) xs[i] = x[(size_t)row0 * C + i];
    __syncthreads();

    const float2* Ws2 = (const float2*)Ws;
    float2 as2 = ((const float2*)att_src)[lane];
    float2 ad2 = ((const float2*)att_dst)[lane];

    #pragma unroll
    for (int rr = 0; rr < 4; rr++) {
        int r = wg * 4 + rr;
        if (r >= nrows) break;
        float2 acc = make_float2(0.0f, 0.0f);
        #pragma unroll
        for (int k = 0; k < C; k++) {
            float xv = xs[r * C + k];
            float2 w = Ws2[k * 32 + lane];
            acc.x = fmaf(xv, w.x, acc.x);
            acc.y = fmaf(xv, w.y, acc.y);
        }
        gy_h2[(size_t)(row0 + r) * (C / 2) + lane] =
            __floats2half2_rn(acc.x, acc.y);
        float ps = acc.x * as2.x + acc.y * as2.y;
        float pd = acc.x * ad2.x + acc.y * ad2.y;
        #pragma unroll
        for (int o = 16; o > 0; o >>= 1) {
            ps += __shfl_down_sync(0xffffffffu, ps, o);
            pd += __shfl_down_sync(0xffffffffu, pd, o);
        }
        if (lane == 0) {
            gy_asrc[row0 + r] = ps;
            gy_adst[row0 + r] = pd;
        }
    }
}

// 3) fused scan + reorder (one kernel, SRB blocks).
//    Blocks [0,NB): phase A block sums -> publish; phase B prefix+off -> publish.
//    All blocks: wait for done==NB, then grid-stride reorder.
__global__ __launch_bounds__(256) void kr_scan_reorder(
    const int* __restrict__ ei, int E, int N, int NB)
{
    __shared__ int sh[256];
    __shared__ int bs[128];
    int t = threadIdx.x;
    int b = blockIdx.x;

    if (b < NB) {
        // phase A: block sum of my 1024 counts
        int base = b * SCHUNK + t * 4;
        int c[4];
        int s = 0;
        #pragma unroll
        for (int k = 0; k < 4; k++) {
            int i = base + k;
            c[k] = (i < N) ? gy_cnt[i] : 0;
            s += c[k];
        }
        sh[t] = s;
        __syncthreads();
        for (int o = 128; o > 0; o >>= 1) {
            if (t < o) sh[t] += sh[t + o];
            __syncthreads();
        }
        if (t == 0) {
            gy_bsum[b] = sh[0];
            __threadfence();
            atomicAdd(&gy_ready, 1);
        }
        // wait all block sums
        if (t == 0) {
            while (atomicAdd(&gy_ready, 0) < NB) __nanosleep(32);
        }
        __syncthreads();
        __threadfence();

        // phase B: prefix of block sums (redundant per block), then my offsets
        if (t < 128) bs[t] = (t < NB) ? gy_bsum[t] : 0;
        __syncthreads();
        for (int o = 1; o < 128; o <<= 1) {
            int u = (t < 128 && t >= o) ? bs[t - o] : 0;
            __syncthreads();
            if (t < 128) bs[t] += u;
            __syncthreads();
        }
        int base0 = (b == 0) ? 0 : bs[b - 1];

        sh[t] = s;   // re-reduce inclusive thread prefix
        __syncthreads();
        for (int o = 1; o < 256; o <<= 1) {
            int u = (t >= o) ? sh[t - o] : 0;
            __syncthreads();
            sh[t] += u;
            __syncthreads();
        }
        int excl = base0 + sh[t] - s;
        #pragma unroll
        for (int k = 0; k < 4; k++) {
            int i = base + k;
            if (i < N) {
                gy_off[i] = excl;
                excl += c[k];
            }
        }
        __threadfence();
        __syncthreads();
        if (t == 0) atomicAdd(&gy_done, 1);
    }

    // all blocks: wait for offsets
    if (t == 0) {
        while (atomicAdd(&gy_done, 0) < NB) __nanosleep(32);
    }
    __syncthreads();
    __threadfence();

    // reorder (grid-stride over all SRB blocks)
    int is64 = gy_is64;
    int tid0 = b * blockDim.x + t;
    int stride = SRB * blockDim.x;
    if (!is64) {
        const int4* src4 = (const int4*)ei;
        const int4* dst4 = (const int4*)(ei + E);
        int E4 = E >> 2;
        for (int i = tid0; i < E4; i += stride) {
            int4 s4 = src4[i];
            int4 d4 = dst4[i];
            int ss[4] = {s4.x, s4.y, s4.z, s4.w};
            int dd[4] = {d4.x, d4.y, d4.z, d4.w};
            #pragma unroll
            for (int k = 0; k < 4; k++) {
                int s = ((unsigned)ss[k] < (unsigned)N) ? ss[k] : 0;
                int d = ((unsigned)dd[k] < (unsigned)N) ? dd[k] : 0;
                float v = gy_asrc[s] + gy_adst[d];
                v = (v > 0.0f) ? v : NEG_SLOPE * v;
                float ex = __expf(v);
                int p = atomicAdd(&gy_off[d], 1);
                gy_se[p] = make_int2(s, __float_as_int(ex));
            }
        }
        for (int i = (E4 << 2) + tid0; i < E; i += stride) {
            int s = ei[i], d = ei[E + i];
            s = ((unsigned)s < (unsigned)N) ? s : 0;
            d = ((unsigned)d < (unsigned)N) ? d : 0;
            float v = gy_asrc[s] + gy_adst[d];
            v = (v > 0.0f) ? v : NEG_SLOPE * v;
            float ex = __expf(v);
            int p = atomicAdd(&gy_off[d], 1);
            gy_se[p] = make_int2(s, __float_as_int(ex));
        }
    } else {
        const long long* el = (const long long*)ei;
        for (int i = tid0; i < E; i += stride) {
            int s = (int)el[i], d = (int)el[E + i];
            s = ((unsigned)s < (unsigned)N) ? s : 0;
            d = ((unsigned)d < (unsigned)N) ? d : 0;
            float v = gy_asrc[s] + gy_adst[d];
            v = (v > 0.0f) ? v : NEG_SLOPE * v;
            float ex = __expf(v);
            int p = atomicAdd(&gy_off[d], 1);
            gy_se[p] = make_int2(s, __float_as_int(ex));
        }
    }
}

// 4) gather: one warp per dst; 4-edge unrolled, fused denom,
//    out = tanh((Σ e·h)/(Σ e + EPS) + bias). Segment = [off[d-1], off[d]).
__global__ __launch_bounds__(256) void kr_gather(
    float* __restrict__ out, const float* __restrict__ bias, int N)
{
    int warp = (blockIdx.x * blockDim.x + threadIdx.x) >> 5;
    int lane = threadIdx.x & 31;
    if (warp >= N) return;
    int beg = (warp == 0) ? 0 : gy_off[warp - 1];
    int end = gy_off[warp];

    float ds = 0.0f;
    float2 acc = make_float2(0.0f, 0.0f);
    int j = beg;

    if ((j & 1) && j < end) {
        int2 se = gy_se[j];
        float e = __int_as_float(se.y);
        ds += e;
        float2 hv = __half22float2(gy_h2[(size_t)se.x * (C / 2) + lane]);
        acc.x = fmaf(e, hv.x, acc.x);
        acc.y = fmaf(e, hv.y, acc.y);
        j++;
    }
    for (; j + 3 < end; j += 4) {
        int4 pA = *(const int4*)&gy_se[j];
        int4 pB = *(const int4*)&gy_se[j + 2];
        float e0 = __int_as_float(pA.y);
        float e1 = __int_as_float(pA.w);
        float e2 = __int_as_float(pB.y);
        float e3 = __int_as_float(pB.w);
        float2 h0 = __half22float2(gy_h2[(size_t)pA.x * (C / 2) + lane]);
        float2 h1 = __half22float2(gy_h2[(size_t)pA.z * (C / 2) + lane]);
        float2 h2 = __half22float2(gy_h2[(size_t)pB.x * (C / 2) + lane]);
        float2 h3 = __half22float2(gy_h2[(size_t)pB.z * (C / 2) + lane]);
        ds += (e0 + e1) + (e2 + e3);
        acc.x = fmaf(e0, h0.x, acc.x);  acc.y = fmaf(e0, h0.y, acc.y);
        acc.x = fmaf(e1, h1.x, acc.x);  acc.y = fmaf(e1, h1.y, acc.y);
        acc.x = fmaf(e2, h2.x, acc.x);  acc.y = fmaf(e2, h2.y, acc.y);
        acc.x = fmaf(e3, h3.x, acc.x);  acc.y = fmaf(e3, h3.y, acc.y);
    }
    for (; j < end; j++) {
        int2 se = gy_se[j];
        float e = __int_as_float(se.y);
        ds += e;
        float2 hv = __half22float2(gy_h2[(size_t)se.x * (C / 2) + lane]);
        acc.x = fmaf(e, hv.x, acc.x);
        acc.y = fmaf(e, hv.y, acc.y);
    }
    float inv = 1.0f / (ds + EPS);
    float2 r;
    r.x = tanhf(fmaf(acc.x, inv, bias[lane * 2 + 0]));
    r.y = tanhf(fmaf(acc.y, inv, bias[lane * 2 + 1]));
    *(float2*)&out[(size_t)warp * C + lane * 2] = r;
}

extern "C" void kernel_launch(void* const* d_in, const int* in_sizes, int n_in,
                              void* d_out, int out_size)
{
    const float* x       = (const float*)d_in[0];
    const int*   ei      = (const int*)d_in[1];
    const float* W       = (const float*)d_in[2];
    const float* att_src = (const float*)d_in[3];
    const float* att_dst = (const float*)d_in[4];
    const float* bias    = (const float*)d_in[5];
    float* out = (float*)d_out;

    int N = in_sizes[0] / C;
    int E = in_sizes[1] / 2;

    int gridN = (N + 255) / 256;
    int gemmB = (N + 31) / 32;
    int NB = (N + SCHUNK - 1) / SCHUNK;

    kr_init<<<gridN, 256>>>(ei, N);
    kr_gemm_hist<<<HB + gemmB, 256>>>(x, W, att_src, att_dst, ei, E, N);
    kr_scan_reorder<<<SRB, 256>>>(ei, E, N, NB);
    kr_gather<<<(N * 32 + 255) / 256, 256>>>(out, bias, N);
}